// round 11
// baseline (speedup 1.0000x reference)
#include <cuda_runtime.h>
#include <cstdint>
#include <math.h>

#define Bn 64
#define Sn 512
#define Dn 768
#define BSn (Bn * Sn)

#define PAD_ID 0
#define SEP_ID 103
#define IGNORE_ID 100

#define NBLK 296              // 2 CTAs per SM on 148 SMs
#define NWARP (NBLK * 8)      // 2368 global warps
#define DEPTH 4               // cp.async ring depth per warp

#define NEG_BIG (-1.0e30f)

// Scratch (no cudaMalloc allowed)
__device__ float g_em[BSn * 2];        // emissions (B,S,2)
__device__ float g_llh[Bn];            // per-batch log-likelihood
__device__ int g_done;                 // loss blocks finished

// ---------------------------------------------------------------------------
// Kernel 1: em = relu((seq * mask) @ W^T + b); also labels_m and mask outputs.
// Persistent grid, warp-per-token, depth-4 cp.async ring. (R7-proven)
// ---------------------------------------------------------------------------
__global__ __launch_bounds__(256, 2) void emissions_kernel(
    const float* __restrict__ seq,
    const int* __restrict__ ids,
    const int* __restrict__ labels,
    const float* __restrict__ W,
    const float* __restrict__ bvec,
    float* __restrict__ out,
    int out_size)
{
    extern __shared__ float4 sbuf[];   // [8 warps][DEPTH][192 float4]

    const int tid  = threadIdx.x;
    const int warp = tid >> 5;
    const int lane = tid & 31;

    if (blockIdx.x == 0 && tid == 0) g_done = 0;

    float4 w0[6], w1[6];
    const float4* W4 = reinterpret_cast<const float4*>(W);
#pragma unroll
    for (int k = 0; k < 6; k++) {
        w0[k] = W4[lane + 32 * k];
        w1[k] = W4[192 + lane + 32 * k];
    }
    const float b0 = bvec[0];
    const float b1 = bvec[1];

    const int gw   = blockIdx.x * 8 + warp;
    const int ntok = (BSn - gw + NWARP - 1) / NWARP;

    int myid = 0, mylab = 0;
    if (lane < ntok) {
        int t = gw + lane * NWARP;
        myid  = ids[t];
        mylab = labels[t];
    }

    float4* mybuf = sbuf + (size_t)warp * DEPTH * 192;

    auto issue = [&](int i) {
        if (i < ntok) {
            int t = gw + i * NWARP;
            const float4* g = reinterpret_cast<const float4*>(seq + (size_t)t * Dn) + lane;
            uint32_t sm = (uint32_t)__cvta_generic_to_shared(mybuf + (i & (DEPTH - 1)) * 192 + lane);
#pragma unroll
            for (int k = 0; k < 6; k++) {
                asm volatile("cp.async.cg.shared.global [%0], [%1], 16;\n"
                             :: "r"(sm + k * 32 * 16), "l"(g + k * 32) : "memory");
            }
        }
        asm volatile("cp.async.commit_group;\n" ::: "memory");
    };

    issue(0); issue(1); issue(2); issue(3);

    for (int i = 0; i < ntok; i++) {
        asm volatile("cp.async.wait_group 3;\n" ::: "memory");
        const float4* xb = mybuf + (i & (DEPTH - 1)) * 192;

        float s0 = 0.f, s1 = 0.f;
#pragma unroll
        for (int k = 0; k < 6; k++) {
            float4 x = xb[lane + 32 * k];
            s0 += x.x * w0[k].x + x.y * w0[k].y + x.z * w0[k].z + x.w * w0[k].w;
            s1 += x.x * w1[k].x + x.y * w1[k].y + x.z * w1[k].z + x.w * w1[k].w;
        }

        issue(i + 4);

#pragma unroll
        for (int off = 16; off; off >>= 1) {
            s0 += __shfl_down_sync(0xFFFFFFFFu, s0, off);
            s1 += __shfl_down_sync(0xFFFFFFFFu, s1, off);
        }
        int id_i  = __shfl_sync(0xFFFFFFFFu, myid, i);
        int lab_i = __shfl_sync(0xFFFFFFFFu, mylab, i);

        if (lane == 0) {
            int t = gw + i * NWARP;
            bool m = (id_i != PAD_ID) && (id_i != SEP_ID) && (lab_i != IGNORE_ID);
            float dot0 = m ? s0 : 0.f;
            float dot1 = m ? s1 : 0.f;
            g_em[t * 2 + 0] = fmaxf(dot0 + b0, 0.f);
            g_em[t * 2 + 1] = fmaxf(dot1 + b1, 0.f);
            if (out_size >= 1 + 3 * BSn) {
                out[1 + BSn + t]     = m ? (float)lab_i : 0.f;
                out[1 + 2 * BSn + t] = m ? 1.f : 0.f;
            }
        }
    }

    __threadfence();
    cudaTriggerProgrammaticLaunchCompletion();
}

// ---------------------------------------------------------------------------
// helpers
// ---------------------------------------------------------------------------
__device__ __forceinline__ float lse2f(float a, float b) {   // fast, MUFU-based
    float m = fmaxf(a, b);
    float n = fminf(a, b);
    return m + __logf(1.f + __expf(n - m));
}
__device__ __forceinline__ float4 lsemm(float4 A, float4 B) {
    float4 C;
    C.x = lse2f(A.x + B.x, A.y + B.z);
    C.y = lse2f(A.x + B.y, A.y + B.w);
    C.z = lse2f(A.z + B.x, A.w + B.z);
    C.w = lse2f(A.z + B.y, A.w + B.w);
    return C;
}
// max-plus 2x2 matmul, A earlier
__device__ __forceinline__ float4 mpmm(float4 A, float4 B) {
    float4 C;
    C.x = fmaxf(A.x + B.x, A.y + B.z);
    C.y = fmaxf(A.x + B.y, A.y + B.w);
    C.z = fmaxf(A.z + B.x, A.w + B.z);
    C.w = fmaxf(A.z + B.y, A.w + B.w);
    return C;
}
// compose tag maps (2-bit encoding, bit x = f(x)): (f o g)(x) = f(g(x))
__device__ __forceinline__ int mapcomp(int f, int g) {
    int h0 = (f >> (g & 1)) & 1;
    int h1 = (f >> ((g >> 1) & 1)) & 1;
    return h0 | (h1 << 1);
}
__device__ __forceinline__ float4 shfl_down_f4(float4 v, int off) {
    float4 r;
    r.x = __shfl_down_sync(0xFFFFFFFFu, v.x, off);
    r.y = __shfl_down_sync(0xFFFFFFFFu, v.y, off);
    r.z = __shfl_down_sync(0xFFFFFFFFu, v.z, off);
    r.w = __shfl_down_sync(0xFFFFFFFFu, v.w, off);
    return r;
}
__device__ __forceinline__ float4 shfl_up_f4(float4 v, int off) {
    float4 r;
    r.x = __shfl_up_sync(0xFFFFFFFFu, v.x, off);
    r.y = __shfl_up_sync(0xFFFFFFFFu, v.y, off);
    r.z = __shfl_up_sync(0xFFFFFFFFu, v.z, off);
    r.w = __shfl_up_sync(0xFFFFFFFFu, v.w, off);
    return r;
}

// ---------------------------------------------------------------------------
// Kernel 2: CRF. 128 blocks x 256 threads.
//  blocks [0, 64):   Viterbi — warp-shuffle max-plus scan, in-register
//                    backpointers, warp-shuffle map suffix scan (3 barriers).
//  blocks [64, 128): logZ + gold + loss; per-batch g_llh store, last block sums.
// ---------------------------------------------------------------------------
__global__ __launch_bounds__(256) void crf_kernel(
    const int* __restrict__ ids,
    const int* __restrict__ labels,
    const float* __restrict__ startt,
    const float* __restrict__ endt,
    const float* __restrict__ trans,
    float* __restrict__ out,
    int out_size)
{
    __shared__ float  semv[Sn][2];    // emissions
    __shared__ int    sM[Sn];         // backpointer maps
    __shared__ int    stag[Sn];       // gold tags (loss)
    __shared__ float4 swtot[8];       // warp scan totals (max-plus)
    __shared__ int    swtotM[8];      // warp scan totals (maps)
    __shared__ float4 swmat[8];
    __shared__ float  swsum[8];
    __shared__ int    slast;

    const int bid  = blockIdx.x;
    const int tid  = threadIdx.x;
    const int lane = tid & 31;
    const int warp = tid >> 5;

    // PDL prologue: g_em-independent work overlaps the emissions tail.
    const float t00 = trans[0], t01 = trans[1], t10 = trans[2], t11 = trans[3];
    const float st0 = startt[0], st1 = startt[1];
    const float en0 = endt[0],   en1 = endt[1];

    if (bid >= 64) {
        const int b = bid - 64;
        for (int s = tid; s < Sn; s += 256) {
            int id  = ids[(size_t)b * Sn + s];
            int lab = labels[(size_t)b * Sn + s];
            bool m = (id != PAD_ID) && (id != SEP_ID) && (lab != IGNORE_ID);
            stag[s] = m ? lab : 0;
        }
    }

    cudaGridDependencySynchronize();

    // =======================================================================
    // VITERBI role: blocks [0, 64)
    // =======================================================================
    if (bid < 64) {
        const int b = bid;

        reinterpret_cast<float4*>(semv)[tid] =
            reinterpret_cast<const float4*>(g_em + (size_t)b * Sn * 2)[tid];
        __syncthreads();

        // ---- max-plus prefix scan via warp shuffles (elems 2k, 2k+1) ----
        const int i0 = 2 * tid, i1 = 2 * tid + 1;
        float4 A;                                   // leaf(i0): I at 0, M_i else
        if (i0 == 0) { A.x = 0.f; A.y = NEG_BIG; A.z = NEG_BIG; A.w = 0.f; }
        else {
            float e0 = semv[i0][0], e1 = semv[i0][1];
            A.x = t00 + e0; A.y = t01 + e1; A.z = t10 + e0; A.w = t11 + e1;
        }
        float4 Bm;                                  // leaf(i1)
        {
            float e0 = semv[i1][0], e1 = semv[i1][1];
            Bm.x = t00 + e0; Bm.y = t01 + e1; Bm.z = t10 + e0; Bm.w = t11 + e1;
        }
        float4 S = mpmm(A, Bm);
#pragma unroll
        for (int off = 1; off <= 16; off <<= 1) {
            float4 p = shfl_up_f4(S, off);
            if (lane >= off) S = mpmm(p, S);
        }
        if (lane == 31) swtot[warp] = S;
        __syncthreads();
        float4 E; E.x = 0.f; E.y = NEG_BIG; E.z = NEG_BIG; E.w = 0.f;
        for (int j = 0; j < warp; j++) E = mpmm(E, swtot[j]);

        float4 Sprev = shfl_up_f4(S, 1);
        if (lane == 0) { Sprev.x = 0.f; Sprev.y = NEG_BIG; Sprev.z = NEG_BIG; Sprev.w = 0.f; }

        float4 Pm1 = mpmm(E, Sprev);                // prefix through i0-1
        float4 P0  = mpmm(Pm1, A);                  // prefix through i0
        float4 P1  = mpmm(E, S);                    // prefix through i1

        const float sa0 = st0 + semv[0][0];
        const float sa1 = st1 + semv[0][1];

        // alpha_{i0-1}, alpha_{i0} in registers — no smem round trip
        float am0 = fmaxf(sa0 + Pm1.x, sa1 + Pm1.z);
        float am1 = fmaxf(sa0 + Pm1.y, sa1 + Pm1.w);
        float a00 = fmaxf(sa0 + P0.x,  sa1 + P0.z);
        float a01 = fmaxf(sa0 + P0.y,  sa1 + P0.w);

        // backpointer maps: m_t(tag_t) = tag_{t-1}; t=0 -> identity
        int m0;
        if (tid == 0) m0 = 2;
        else {
            int c0 = (am1 + t10 > am0 + t00) ? 1 : 0;
            int c1 = (am1 + t11 > am0 + t01) ? 1 : 0;
            m0 = c0 | (c1 << 1);
        }
        int m1;
        {
            int c0 = (a01 + t10 > a00 + t00) ? 1 : 0;
            int c1 = (a01 + t11 > a00 + t01) ? 1 : 0;
            m1 = c0 | (c1 << 1);
        }
        sM[i0] = m0;
        sM[i1] = m1;
        if (i1 == Sn - 1) {
            float f0 = fmaxf(sa0 + P1.x, sa1 + P1.z) + en0;
            float f1 = fmaxf(sa0 + P1.y, sa1 + P1.w) + en1;
            slast = (f1 > f0) ? 1 : 0;
        }
        __syncthreads();

        // ---- suffix map scan via warp shuffles (reversed index; R8-proven) ----
        const int j0 = 2 * tid, j1 = 2 * tid + 1;
        int n0 = sM[Sn - 1 - j0];
        int n1 = sM[Sn - 1 - j1];
        int L = mapcomp(n1, n0);                    // op(n0, n1)
#pragma unroll
        for (int off = 1; off <= 16; off <<= 1) {
            int p = __shfl_up_sync(0xFFFFFFFFu, L, off);
            if (lane >= off) L = mapcomp(L, p);     // op(p, L)
        }
        if (lane == 31) swtotM[warp] = L;
        __syncthreads();
        int EM = 2;                                 // identity
        for (int j = 0; j < warp; j++) EM = mapcomp(swtotM[j], EM);

        int Lprev = __shfl_up_sync(0xFFFFFFFFu, L, 1);
        if (lane == 0) Lprev = 2;
        int Q1 = mapcomp(L, EM);                    // S[511-j1]
        int Q0 = mapcomp(n0, mapcomp(Lprev, EM));   // S[511-j0]

        if (out_size >= 1 + BSn) {
            int last = slast;
            int ta = 510 - j0;
            out[1 + (size_t)b * Sn + ta] = (float)((Q0 >> last) & 1);
            if (j1 <= 510) {
                int tb = 510 - j1;
                out[1 + (size_t)b * Sn + tb] = (float)((Q1 >> last) & 1);
            } else {
                out[1 + (size_t)b * Sn + (Sn - 1)] = (float)last;
            }
        }
        return;
    }

    // =======================================================================
    // LOSS role: blocks [64, 128)
    // =======================================================================
    {
        const int b = bid - 64;

        reinterpret_cast<float4*>(semv)[tid] =
            reinterpret_cast<const float4*>(g_em + (size_t)b * Sn * 2)[tid];
        __syncthreads();

        // gold partial (2 tokens/thread) + warp reduce
        float gpart = 0.f;
        {
            int s = tid;
            int a = stag[s];
            gpart += semv[s][a];
            int c = stag[s + 1];
            gpart += (a == 0) ? (c == 0 ? t00 : t01) : (c == 0 ? t10 : t11);
            s = tid + 256;
            a = stag[s];
            gpart += semv[s][a];
            if (s < Sn - 1) {
                c = stag[s + 1];
                gpart += (a == 0) ? (c == 0 ? t00 : t01) : (c == 0 ? t10 : t11);
            }
        }
#pragma unroll
        for (int off = 16; off; off >>= 1)
            gpart += __shfl_down_sync(0xFFFFFFFFu, gpart, off);
        if (lane == 0) swsum[warp] = gpart;

        // lse leaf (t = 2*tid+1, 2*tid+2) + ordered warp tree
        {
            int t0 = 2 * tid + 1;
            float4 Mv;
            float e0 = semv[t0][0], e1 = semv[t0][1];
            Mv.x = t00 + e0; Mv.y = t01 + e1;
            Mv.z = t10 + e0; Mv.w = t11 + e1;
            int t1 = 2 * tid + 2;
            if (t1 <= Sn - 1) {
                float4 Mb;
                e0 = semv[t1][0]; e1 = semv[t1][1];
                Mb.x = t00 + e0; Mb.y = t01 + e1;
                Mb.z = t10 + e0; Mb.w = t11 + e1;
                Mv = lsemm(Mv, Mb);
            }
#pragma unroll
            for (int off = 1; off <= 16; off <<= 1) {
                float4 o = shfl_down_f4(Mv, off);
                Mv = lsemm(Mv, o);
            }
            if (lane == 0) swmat[warp] = Mv;
        }
        __syncthreads();

        if (warp == 0) {
            float4 m;
            if (lane < 8) m = swmat[lane];
            else { m.x = 0.f; m.y = NEG_BIG; m.z = NEG_BIG; m.w = 0.f; }
            float gs = (lane < 8) ? swsum[lane] : 0.f;
#pragma unroll
            for (int off = 1; off <= 4; off <<= 1) {
                float4 o = shfl_down_f4(m, off);
                m = lsemm(m, o);
                gs += __shfl_down_sync(0xFFFFFFFFu, gs, off);
            }
            if (lane == 0) {
                float score = gs + ((stag[0] == 0) ? st0 : st1)
                                 + ((stag[Sn - 1] == 0) ? en0 : en1);
                float a0 = st0 + semv[0][0];
                float a1 = st1 + semv[0][1];
                float f0 = lse2f(a0 + m.x, a1 + m.z);
                float f1 = lse2f(a0 + m.y, a1 + m.w);
                float logZ = lse2f(f0 + en0, f1 + en1);
                g_llh[b] = score - logZ;
                __threadfence();
                int old = atomicAdd(&g_done, 1);
                if (old == Bn - 1) {           // last arriver finalizes
                    __threadfence();
                    double s = 0.0;
#pragma unroll 8
                    for (int i = 0; i < Bn; i++) s += (double)g_llh[i];
                    out[0] = (float)(s / (double)BSn);
                }
            }
        }
        return;
    }
}

// ---------------------------------------------------------------------------
extern "C" void kernel_launch(void* const* d_in, const int* in_sizes, int n_in,
                              void* d_out, int out_size)
{
    const float* seq    = (const float*)d_in[0];
    const int*   ids    = (const int*)d_in[1];
    const int*   labels = (const int*)d_in[2];
    const float* W      = (const float*)d_in[3];
    const float* bvec   = (const float*)d_in[4];
    const float* startt = (const float*)d_in[5];
    const float* endt   = (const float*)d_in[6];
    const float* trans  = (const float*)d_in[7];
    float* out = (float*)d_out;

    const int smem = 8 * DEPTH * 192 * 16;  // 98304 B dynamic (emissions rings)
    static int configured = 0;
    if (!configured) {
        cudaFuncSetAttribute(emissions_kernel,
                             cudaFuncAttributeMaxDynamicSharedMemorySize, smem);
        configured = 1;
    }

    emissions_kernel<<<NBLK, 256, smem>>>(seq, ids, labels, W, bvec, out, out_size);

    cudaLaunchConfig_t cfg = {};
    cfg.gridDim  = dim3(128, 1, 1);
    cfg.blockDim = dim3(256, 1, 1);
    cfg.dynamicSmemBytes = 0;
    cfg.stream = 0;
    cudaLaunchAttribute attrs[1];
    attrs[0].id = cudaLaunchAttributeProgrammaticStreamSerialization;
    attrs[0].val.programmaticStreamSerializationAllowed = 1;
    cfg.attrs = attrs;
    cfg.numAttrs = 1;

    cudaError_t err = cudaLaunchKernelEx(&cfg, crf_kernel,
                                         ids, labels, startt, endt, trans,
                                         out, out_size);
    if (err != cudaSuccess) {
        crf_kernel<<<128, 256>>>(ids, labels, startt, endt, trans, out, out_size);
    }
}

// round 13
// speedup vs baseline: 1.2314x; 1.2314x over previous
#include <cuda_runtime.h>
#include <cstdint>
#include <math.h>

#define Bn 64
#define Sn 512
#define Dn 768
#define BSn (Bn * Sn)

#define PAD_ID 0
#define SEP_ID 103
#define IGNORE_ID 100

#define NBLK 296              // 2 CTAs per SM on 148 SMs
#define NWARP (NBLK * 8)      // 2368 global warps
#define DEPTH 4               // cp.async ring depth per warp

#define NEG_BIG (-1.0e30f)

// Scratch (no cudaMalloc allowed)
__device__ float g_em[BSn * 2];            // emissions (B,S,2)
__device__ unsigned long long g_acc;       // fixed-point llh accumulator
__device__ int g_done;                     // loss warps finished

// named barriers: viterbi half (warps 0-7) id 1, loss half (warps 8-15) id 2
#define BARV() asm volatile("bar.sync 1, 256;" ::: "memory")
#define BARL() asm volatile("bar.sync 2, 256;" ::: "memory")

// ---------------------------------------------------------------------------
// Kernel 1: em = relu((seq * mask) @ W^T + b); also labels_m and mask outputs.
// Persistent grid, warp-per-token, depth-4 cp.async ring. (R7-proven, frozen)
// ---------------------------------------------------------------------------
__global__ __launch_bounds__(256, 2) void emissions_kernel(
    const float* __restrict__ seq,
    const int* __restrict__ ids,
    const int* __restrict__ labels,
    const float* __restrict__ W,
    const float* __restrict__ bvec,
    float* __restrict__ out,
    int out_size)
{
    extern __shared__ float4 sbuf[];   // [8 warps][DEPTH][192 float4]

    const int tid  = threadIdx.x;
    const int warp = tid >> 5;
    const int lane = tid & 31;

    if (blockIdx.x == 0 && tid == 0) { g_acc = 0ULL; g_done = 0; }

    float4 w0[6], w1[6];
    const float4* W4 = reinterpret_cast<const float4*>(W);
#pragma unroll
    for (int k = 0; k < 6; k++) {
        w0[k] = W4[lane + 32 * k];
        w1[k] = W4[192 + lane + 32 * k];
    }
    const float b0 = bvec[0];
    const float b1 = bvec[1];

    const int gw   = blockIdx.x * 8 + warp;
    const int ntok = (BSn - gw + NWARP - 1) / NWARP;

    int myid = 0, mylab = 0;
    if (lane < ntok) {
        int t = gw + lane * NWARP;
        myid  = ids[t];
        mylab = labels[t];
    }

    float4* mybuf = sbuf + (size_t)warp * DEPTH * 192;

    auto issue = [&](int i) {
        if (i < ntok) {
            int t = gw + i * NWARP;
            const float4* g = reinterpret_cast<const float4*>(seq + (size_t)t * Dn) + lane;
            uint32_t sm = (uint32_t)__cvta_generic_to_shared(mybuf + (i & (DEPTH - 1)) * 192 + lane);
#pragma unroll
            for (int k = 0; k < 6; k++) {
                asm volatile("cp.async.cg.shared.global [%0], [%1], 16;\n"
                             :: "r"(sm + k * 32 * 16), "l"(g + k * 32) : "memory");
            }
        }
        asm volatile("cp.async.commit_group;\n" ::: "memory");
    };

    issue(0); issue(1); issue(2); issue(3);

    for (int i = 0; i < ntok; i++) {
        asm volatile("cp.async.wait_group 3;\n" ::: "memory");
        const float4* xb = mybuf + (i & (DEPTH - 1)) * 192;

        float s0 = 0.f, s1 = 0.f;
#pragma unroll
        for (int k = 0; k < 6; k++) {
            float4 x = xb[lane + 32 * k];
            s0 += x.x * w0[k].x + x.y * w0[k].y + x.z * w0[k].z + x.w * w0[k].w;
            s1 += x.x * w1[k].x + x.y * w1[k].y + x.z * w1[k].z + x.w * w1[k].w;
        }

        issue(i + 4);

#pragma unroll
        for (int off = 16; off; off >>= 1) {
            s0 += __shfl_down_sync(0xFFFFFFFFu, s0, off);
            s1 += __shfl_down_sync(0xFFFFFFFFu, s1, off);
        }
        int id_i  = __shfl_sync(0xFFFFFFFFu, myid, i);
        int lab_i = __shfl_sync(0xFFFFFFFFu, mylab, i);

        if (lane == 0) {
            int t = gw + i * NWARP;
            bool m = (id_i != PAD_ID) && (id_i != SEP_ID) && (lab_i != IGNORE_ID);
            float dot0 = m ? s0 : 0.f;
            float dot1 = m ? s1 : 0.f;
            g_em[t * 2 + 0] = fmaxf(dot0 + b0, 0.f);
            g_em[t * 2 + 1] = fmaxf(dot1 + b1, 0.f);
            if (out_size >= 1 + 3 * BSn) {
                out[1 + BSn + t]     = m ? (float)lab_i : 0.f;
                out[1 + 2 * BSn + t] = m ? 1.f : 0.f;
            }
        }
    }
}

// ---------------------------------------------------------------------------
// helpers (R7-proven, frozen)
// ---------------------------------------------------------------------------
__device__ __forceinline__ float lse2f(float a, float b) {   // fast, MUFU-based
    float m = fmaxf(a, b);
    float n = fminf(a, b);
    return m + __logf(1.f + __expf(n - m));
}
__device__ __forceinline__ float4 lsemm(float4 A, float4 B) {
    float4 C;
    C.x = lse2f(A.x + B.x, A.y + B.z);
    C.y = lse2f(A.x + B.y, A.y + B.w);
    C.z = lse2f(A.z + B.x, A.w + B.z);
    C.w = lse2f(A.z + B.y, A.w + B.w);
    return C;
}
// max-plus 2x2 matmul, A earlier
__device__ __forceinline__ float4 mpmm(float4 A, float4 B) {
    float4 C;
    C.x = fmaxf(A.x + B.x, A.y + B.z);
    C.y = fmaxf(A.x + B.y, A.y + B.w);
    C.z = fmaxf(A.z + B.x, A.w + B.z);
    C.w = fmaxf(A.z + B.y, A.w + B.w);
    return C;
}
// compose tag maps (2-bit encoding, bit x = f(x)): (f o g)(x) = f(g(x))
__device__ __forceinline__ int mapcomp(int f, int g) {
    int h0 = (f >> (g & 1)) & 1;
    int h1 = (f >> ((g >> 1) & 1)) & 1;
    return h0 | (h1 << 1);
}
__device__ __forceinline__ float4 shfl_down_f4(float4 v, int off) {
    float4 r;
    r.x = __shfl_down_sync(0xFFFFFFFFu, v.x, off);
    r.y = __shfl_down_sync(0xFFFFFFFFu, v.y, off);
    r.z = __shfl_down_sync(0xFFFFFFFFu, v.z, off);
    r.w = __shfl_down_sync(0xFFFFFFFFu, v.w, off);
    return r;
}
__device__ __forceinline__ float4 shfl_up_f4(float4 v, int off) {
    float4 r;
    r.x = __shfl_up_sync(0xFFFFFFFFu, v.x, off);
    r.y = __shfl_up_sync(0xFFFFFFFFu, v.y, off);
    r.z = __shfl_up_sync(0xFFFFFFFFu, v.z, off);
    r.w = __shfl_up_sync(0xFFFFFFFFu, v.w, off);
    return r;
}

// ---------------------------------------------------------------------------
// Kernel 2: CRF. 64 blocks x 512 threads — one block per batch.
//  warps 0-7  (tid 0..255):   Viterbi decode (R7 code, bar.sync 1)
//  warps 8-15 (tid 256..511): logZ + gold + loss (R7 code, bar.sync 2)
// Shared semv loaded once per batch.
// ---------------------------------------------------------------------------
__global__ __launch_bounds__(512) void crf_kernel(
    const int* __restrict__ ids,
    const int* __restrict__ labels,
    const float* __restrict__ startt,
    const float* __restrict__ endt,
    const float* __restrict__ trans,
    float* __restrict__ out,
    int out_size)
{
    __shared__ float  semv[Sn][2];    // emissions (shared by both roles)
    __shared__ float  salpha[Sn][2];  // viterbi forward scores
    __shared__ int    sM[2][Sn];      // map scan ping-pong
    __shared__ int    stag[Sn];       // gold tags (loss)
    __shared__ float4 swtot[8];       // viterbi warp scan totals
    __shared__ float4 swmat[8];       // loss lse warp results
    __shared__ float  swsum[8];       // loss gold partials
    __shared__ int    slast;

    const int b    = blockIdx.x;
    const int tid  = threadIdx.x;

    const float t00 = trans[0], t01 = trans[1], t10 = trans[2], t11 = trans[3];

    // loss half loads gold tags; viterbi half loads emissions
    if (tid >= 256) {
        for (int s = tid - 256; s < Sn; s += 256) {
            int id  = ids[(size_t)b * Sn + s];
            int lab = labels[(size_t)b * Sn + s];
            bool m = (id != PAD_ID) && (id != SEP_ID) && (lab != IGNORE_ID);
            stag[s] = m ? lab : 0;
        }
    } else {
        reinterpret_cast<float4*>(semv)[tid] =
            reinterpret_cast<const float4*>(g_em + (size_t)b * Sn * 2)[tid];
    }
    __syncthreads();

    // =======================================================================
    // VITERBI role: warps 0-7 (R7 code; __syncthreads -> BARV)
    // =======================================================================
    if (tid < 256) {
        const int lane = tid & 31;
        const int warp = tid >> 5;

        // ---- max-plus prefix scan via warp shuffles (elems 2k, 2k+1) ----
        const int i0 = 2 * tid, i1 = 2 * tid + 1;
        float4 A;                                   // leaf(i0): I at 0, M_i else
        if (i0 == 0) { A.x = 0.f; A.y = NEG_BIG; A.z = NEG_BIG; A.w = 0.f; }
        else {
            float e0 = semv[i0][0], e1 = semv[i0][1];
            A.x = t00 + e0; A.y = t01 + e1; A.z = t10 + e0; A.w = t11 + e1;
        }
        float4 Bm;                                  // leaf(i1)
        {
            float e0 = semv[i1][0], e1 = semv[i1][1];
            Bm.x = t00 + e0; Bm.y = t01 + e1; Bm.z = t10 + e0; Bm.w = t11 + e1;
        }
        float4 S = mpmm(A, Bm);
#pragma unroll
        for (int off = 1; off <= 16; off <<= 1) {
            float4 p = shfl_up_f4(S, off);
            if (lane >= off) S = mpmm(p, S);
        }
        if (lane == 31) swtot[warp] = S;
        BARV();
        float4 E; E.x = 0.f; E.y = NEG_BIG; E.z = NEG_BIG; E.w = 0.f;
        for (int j = 0; j < warp; j++) E = mpmm(E, swtot[j]);

        float4 Sprev = shfl_up_f4(S, 1);
        if (lane == 0) { Sprev.x = 0.f; Sprev.y = NEG_BIG; Sprev.z = NEG_BIG; Sprev.w = 0.f; }

        float4 P1 = mpmm(E, S);
        float4 P0 = mpmm(mpmm(E, Sprev), A);

        const float sa0 = startt[0] + semv[0][0];
        const float sa1 = startt[1] + semv[0][1];
        salpha[i0][0] = fmaxf(sa0 + P0.x, sa1 + P0.z);
        salpha[i0][1] = fmaxf(sa0 + P0.y, sa1 + P0.w);
        salpha[i1][0] = fmaxf(sa0 + P1.x, sa1 + P1.z);
        salpha[i1][1] = fmaxf(sa0 + P1.y, sa1 + P1.w);
        if (i1 == Sn - 1) {
            float f0 = salpha[i1][0] + endt[0];
            float f1 = salpha[i1][1] + endt[1];
            slast = (f1 > f0) ? 1 : 0;
        }
        BARV();

        // backpointer maps from alpha_{t-1}
        {
            int t = i0;
            if (t == 0) sM[0][0] = 2;   // identity
            else {
                float al0 = salpha[t - 1][0], al1 = salpha[t - 1][1];
                int c0 = (al1 + t10 > al0 + t00) ? 1 : 0;
                int c1 = (al1 + t11 > al0 + t01) ? 1 : 0;
                sM[0][t] = c0 | (c1 << 1);
            }
            t = i1;
            float al0 = salpha[t - 1][0], al1 = salpha[t - 1][1];
            int c0 = (al1 + t10 > al0 + t00) ? 1 : 0;
            int c1 = (al1 + t11 > al0 + t01) ? 1 : 0;
            sM[0][t] = c0 | (c1 << 1);
        }
        BARV();

        // suffix map-composition scan (9 steps)
        int q = 0;
#pragma unroll
        for (int d = 1; d < Sn; d <<= 1) {
            int a0i = tid, a1i = tid + 256;
            int f0v = sM[q][a0i];
            int g0v = (a0i + d < Sn) ? sM[q][a0i + d] : 2;
            int f1v = sM[q][a1i];
            int g1v = (a1i + d < Sn) ? sM[q][a1i + d] : 2;
            sM[q ^ 1][a0i] = mapcomp(f0v, g0v);
            sM[q ^ 1][a1i] = mapcomp(f1v, g1v);
            BARV();
            q ^= 1;
        }

        if (out_size >= 1 + BSn) {
            int last = slast;
            int a0i = tid, a1i = tid + 256;
            int tag0 = (sM[q][a0i + 1] >> last) & 1;
            int tag1 = (a1i == Sn - 1) ? last : ((sM[q][a1i + 1] >> last) & 1);
            out[1 + (size_t)b * Sn + a0i] = (float)tag0;
            out[1 + (size_t)b * Sn + a1i] = (float)tag1;
        }
        return;
    }

    // =======================================================================
    // LOSS role: warps 8-15 (R7 code; __syncthreads -> BARL)
    // =======================================================================
    {
        const int ltid = tid - 256;       // 0..255
        const int lane = ltid & 31;
        const int warp = ltid >> 5;

        // gold partial (2 tokens/thread) + warp reduce
        float gpart = 0.f;
        {
            int s = ltid;
            int a = stag[s];
            gpart += semv[s][a];
            int c = stag[s + 1];
            gpart += (a == 0) ? (c == 0 ? t00 : t01) : (c == 0 ? t10 : t11);
            s = ltid + 256;
            a = stag[s];
            gpart += semv[s][a];
            if (s < Sn - 1) {
                c = stag[s + 1];
                gpart += (a == 0) ? (c == 0 ? t00 : t01) : (c == 0 ? t10 : t11);
            }
        }
#pragma unroll
        for (int off = 16; off; off >>= 1)
            gpart += __shfl_down_sync(0xFFFFFFFFu, gpart, off);
        if (lane == 0) swsum[warp] = gpart;

        // lse leaf (t = 2*ltid+1, 2*ltid+2) + ordered warp tree
        {
            int t0 = 2 * ltid + 1;
            float4 Mv;
            float e0 = semv[t0][0], e1 = semv[t0][1];
            Mv.x = t00 + e0; Mv.y = t01 + e1;
            Mv.z = t10 + e0; Mv.w = t11 + e1;
            int t1 = 2 * ltid + 2;
            if (t1 <= Sn - 1) {
                float4 Mb;
                e0 = semv[t1][0]; e1 = semv[t1][1];
                Mb.x = t00 + e0; Mb.y = t01 + e1;
                Mb.z = t10 + e0; Mb.w = t11 + e1;
                Mv = lsemm(Mv, Mb);
            }
#pragma unroll
            for (int off = 1; off <= 16; off <<= 1) {
                float4 o = shfl_down_f4(Mv, off);
                Mv = lsemm(Mv, o);
            }
            if (lane == 0) swmat[warp] = Mv;
        }
        BARL();

        if (warp == 0) {
            float4 m;
            if (lane < 8) m = swmat[lane];
            else { m.x = 0.f; m.y = NEG_BIG; m.z = NEG_BIG; m.w = 0.f; }
            float gs = (lane < 8) ? swsum[lane] : 0.f;
#pragma unroll
            for (int off = 1; off <= 4; off <<= 1) {
                float4 o = shfl_down_f4(m, off);
                m = lsemm(m, o);
                gs += __shfl_down_sync(0xFFFFFFFFu, gs, off);
            }
            if (lane == 0) {
                float score = gs + startt[stag[0]] + endt[stag[Sn - 1]];
                float a0 = startt[0] + semv[0][0];
                float a1 = startt[1] + semv[0][1];
                float f0 = lse2f(a0 + m.x, a1 + m.z);
                float f1 = lse2f(a0 + m.y, a1 + m.w);
                float logZ = lse2f(f0 + endt[0], f1 + endt[1]);
                float llh = score - logZ;
                long long fx = __double2ll_rn((double)llh * 4294967296.0);
                atomicAdd(&g_acc, (unsigned long long)fx);
                __threadfence();
                int old = atomicAdd(&g_done, 1);
                if (old == Bn - 1) {
                    __threadfence();
                    unsigned long long a = atomicAdd(&g_acc, 0ULL);
                    double s = (double)(long long)a * (1.0 / 4294967296.0);
                    out[0] = (float)(s / (double)BSn);
                }
            }
        }
        return;
    }
}

// ---------------------------------------------------------------------------
extern "C" void kernel_launch(void* const* d_in, const int* in_sizes, int n_in,
                              void* d_out, int out_size)
{
    const float* seq    = (const float*)d_in[0];
    const int*   ids    = (const int*)d_in[1];
    const int*   labels = (const int*)d_in[2];
    const float* W      = (const float*)d_in[3];
    const float* bvec   = (const float*)d_in[4];
    const float* startt = (const float*)d_in[5];
    const float* endt   = (const float*)d_in[6];
    const float* trans  = (const float*)d_in[7];
    float* out = (float*)d_out;

    const int smem = 8 * DEPTH * 192 * 16;  // 98304 B dynamic (emissions rings)
    static int configured = 0;
    if (!configured) {
        cudaFuncSetAttribute(emissions_kernel,
                             cudaFuncAttributeMaxDynamicSharedMemorySize, smem);
        configured = 1;
    }

    emissions_kernel<<<NBLK, 256, smem>>>(seq, ids, labels, W, bvec, out, out_size);
    crf_kernel<<<Bn, 512>>>(ids, labels, startt, endt, trans, out, out_size);
}